// round 13
// baseline (speedup 1.0000x reference)
#include <cuda_runtime.h>
#include <cuda_fp16.h>
#include <math.h>
#include <stdint.h>

// Problem shapes (fixed)
#define B_ 4
#define N_ 4096
#define W_ 1024
#define H_ 16
#define A_ 64
#define HA_ 1024           // H_*A_
#define M_ 16384           // B_*N_
#define NB1 1152           // GEMM1 extended N (1024 values + 48 proj + 80 pad)

// ---------------------------------------------------------------------------
// Scratch (no allocations allowed -> __device__ globals)
// ---------------------------------------------------------------------------
__device__ __half g_valh[M_ * HA_];         // 32 MB (GEMM1 out, fp16)
__device__ __half g_outh[M_ * HA_];         // 32 MB (GEMM2 in, fp16)
__device__ __half g_xh[M_ * W_];            // fp16 x, 32 MB
__device__ __half g_wv_e[NB1 * W_];         // extended GEMM1 B: 2.25 MB
__device__ __half g_wo_h[W_ * HA_];         // 2 MB
__device__ float g_cross[B_ * H_ * N_];
__device__ float g_diag [B_ * H_ * N_];
__device__ float g_extra[B_ * H_ * N_];
__device__ float g_p1 [H_ * N_];
__device__ float g_p2e[H_ * N_];

__device__ __forceinline__ uint32_t s2u(const void* p) {
    uint32_t r;
    asm("{ .reg .u64 t; cvta.to.shared.u64 t, %1; cvt.u32.u64 %0, t; }" : "=r"(r) : "l"(p));
    return r;
}
__device__ __forceinline__ void cp16(uint32_t dst, const void* src) {
    asm volatile("cp.async.cg.shared.global [%0], [%1], 16;" :: "r"(dst), "l"(src));
}
#define CP_COMMIT() asm volatile("cp.async.commit_group;" ::: "memory")
#define CP_WAIT(n)  asm volatile("cp.async.wait_group %0;" :: "n"(n) : "memory")

// ---------------------------------------------------------------------------
// Fused prologue: one launch, blockIdx-range dispatch, 256 threads/block.
//   [0, 8192)            convert_x        (x -> g_xh, 8 elems/thread)
//   [8192, 9216)         transpose_wv     (1024 tiles of 32x32)
//   [9216, 9728)         fill_proj_rows
//   [9728, 11776)        transpose_wo
//   [11776, 12032)       pos_kernel
// ---------------------------------------------------------------------------
#define PB_CONV 8192
#define PB_WV   (PB_CONV + 1024)
#define PB_PROJ (PB_WV + 512)
#define PB_WO   (PB_PROJ + 2048)
#define PB_POS  (PB_WO + 256)

__global__ __launch_bounds__(256) void prologue(const float* __restrict__ x,
                                                const float* __restrict__ vw,
                                                const float* __restrict__ ow,
                                                const float* __restrict__ k1,
                                                const float* __restrict__ k2,
                                                const float* __restrict__ k3,
                                                const float* __restrict__ a1,
                                                const float* __restrict__ a2,
                                                const float* __restrict__ b1,
                                                const float* __restrict__ b2,
                                                const float* __restrict__ cc) {
    int blk = blockIdx.x;
    if (blk < PB_CONV) {
        // ---- convert_x ----
        size_t i = ((size_t)blk * 256 + threadIdx.x) * 8;
        float4 v1 = *(const float4*)(x + i);
        float4 v2 = *(const float4*)(x + i + 4);
        __half2 h0 = __floats2half2_rn(v1.x, v1.y);
        __half2 h1 = __floats2half2_rn(v1.z, v1.w);
        __half2 h2 = __floats2half2_rn(v2.x, v2.y);
        __half2 h3 = __floats2half2_rn(v2.z, v2.w);
        *(uint4*)(g_xh + i) = make_uint4(*(uint32_t*)&h0, *(uint32_t*)&h1,
                                         *(uint32_t*)&h2, *(uint32_t*)&h3);
    } else if (blk < PB_WV) {
        // ---- transpose_wv: tile index -> (h, w0, a0) ----
        __shared__ float tile[32][33];
        int t = blk - PB_CONV;          // 0..1023
        int h = t >> 6;                 // 16 heads (64 tiles each)
        int w0 = ((t >> 1) & 31) * 32;  // 32 w-tiles
        int a0 = (t & 1) * 32;          // 2 a-tiles
        int tx = threadIdx.x & 31;
        int ty = threadIdx.x >> 5;      // 0..7
#pragma unroll
        for (int i = 0; i < 4; i++) {
            int w = w0 + ty + i * 8;
            tile[ty + i * 8][tx] = vw[((h << 10) + w) * 64 + a0 + tx];
        }
        __syncthreads();
#pragma unroll
        for (int i = 0; i < 4; i++) {
            int a = a0 + ty + i * 8;
            g_wv_e[((h << 6) + a) * 1024 + w0 + tx] =
                __float2half_rn(tile[tx][ty + i * 8]);
        }
    } else if (blk < PB_PROJ) {
        // ---- fill_proj_rows ----
        int idx = (blk - PB_WV) * 256 + threadIdx.x;   // 0..131071
        int j = idx >> 10;
        int w = idx & 1023;
        __half v = __float2half(0.f);
        if (j < 48) {
            const float* kk = (j < 16) ? k1 : ((j < 32) ? k2 : k3);
            v = __float2half_rn(kk[(j & 15) * W_ + w]);
        }
        g_wv_e[(size_t)(1024 + j) * 1024 + w] = v;
    } else if (blk < PB_WO) {
        // ---- transpose_wo ----
        int i2 = ((blk - PB_PROJ) * 256 + threadIdx.x) * 2;
        int a = i2 & 63;
        int hq = (i2 >> 6) & 15;
        int w = i2 >> 10;
        float2 v = *(const float2*)(ow + (size_t)(((hq << 10) + w) << 6) + a);
        *(__half2*)(g_wo_h + i2) = __floats2half2_rn(v.x, v.y);
    } else {
        // ---- pos_kernel ----
        int idx = (blk - PB_WO) * 256 + threadIdx.x;   // 0..65535
        int h = idx >> 12;
        int n = idx & (N_ - 1);
        float nv = (float)n * (1.0f / 4095.0f);
        float s1 = 0.f, s2 = 0.f;
#pragma unroll 8
        for (int p = 0; p < 64; p++) {
            float cp = cc[h * 64 + p];
            s1 += sinf(fmaf(a1[h * 64 + p], nv, b1[h * 64 + p])) * cp;
            s2 += sinf(fmaf(a2[h * 64 + p], nv, b2[h * 64 + p])) * cp;
        }
        g_p1[idx] = s1;
        s2 = fminf(fmaxf(s2, -20.f), 20.f);
        g_p2e[idx] = expf(s2);
    }
}

// ---------------------------------------------------------------------------
// fp16 mma.m16n8k16 GEMM, cp.async 4-stage pipeline, prefetch after sync.
//      EPI: 1 = float C, 2 = half C + fused proj tile at bn==8
// ---------------------------------------------------------------------------
#define BK 32
#define KPADH 40
#define KT2 (1024 / BK)
#define STG 4
#define HALF_BYTES (128 * KPADH * 2)
#define STAGE_BYTES (2 * HALF_BYTES)
#define GSMEM (STG * STAGE_BYTES)

__device__ __forceinline__ void mma16816(float* c, const uint32_t* a, const uint32_t* b) {
    asm volatile(
        "mma.sync.aligned.m16n8k16.row.col.f32.f16.f16.f32 "
        "{%0,%1,%2,%3}, {%4,%5,%6,%7}, {%8,%9}, {%0,%1,%2,%3};"
        : "+f"(c[0]), "+f"(c[1]), "+f"(c[2]), "+f"(c[3])
        : "r"(a[0]), "r"(a[1]), "r"(a[2]), "r"(a[3]), "r"(b[0]), "r"(b[1]));
}
__device__ __forceinline__ void ldsm4(uint32_t* r, uint32_t addr) {
    asm volatile("ldmatrix.sync.aligned.m8n8.x4.shared.b16 {%0,%1,%2,%3}, [%4];"
                 : "=r"(r[0]), "=r"(r[1]), "=r"(r[2]), "=r"(r[3]) : "r"(addr));
}

__device__ __forceinline__ void proj_store(float s, int which, int h, int b, int n) {
    s = fminf(fmaxf(s, -20.f), 20.f);
    s = expf(s);
    int off = (b * H_ + h) * N_ + n;
    if (which == 0)      g_cross[off] = s;
    else if (which == 1) g_diag[off]  = s;
    else                 g_extra[off] = s;
}

template <int EPI>
__global__ __launch_bounds__(256, 2) void gemm_f16(const __half* __restrict__ A,
                                                   const __half* __restrict__ Bt,
                                                   void* __restrict__ Cv) {
    extern __shared__ __align__(16) char smem[];
    uint32_t smem_u = s2u(smem);

    int tid = threadIdx.x;
    int lane = tid & 31, wid = tid >> 5;
    int wm = wid >> 2;
    int wn = wid & 3;
    int gid = lane >> 2;
    int tig = lane & 3;
    int lr = lane & 15;
    int lk = (lane >> 4) << 3;

    int bn = blockIdx.x, bm = blockIdx.y;
    const __half* Ag = A + (size_t)(bm * 128) * 1024;
    const __half* Bg = Bt + (size_t)(bn * 128) * 1024;

    int c0row = tid >> 2;
    int c0k = (tid & 3) * 8;

    float c[4][4][4];
#pragma unroll
    for (int i = 0; i < 4; i++)
#pragma unroll
        for (int j = 0; j < 4; j++)
#pragma unroll
            for (int q = 0; q < 4; q++) c[i][j][q] = 0.f;

    auto load_stage = [&](int t, int s) {
        int k0 = t * BK;
        uint32_t base = smem_u + s * STAGE_BYTES;
#pragma unroll
        for (int i = 0; i < 2; i++) {
            int row = c0row + i * 64;
            uint32_t off = (uint32_t)(row * (KPADH * 2) + c0k * 2);
            cp16(base + off, Ag + (size_t)row * 1024 + k0 + c0k);
            cp16(base + HALF_BYTES + off, Bg + (size_t)row * 1024 + k0 + c0k);
        }
    };
    auto ldsm_group = [&](uint32_t af[4][4], uint32_t bf[4][2],
                          uint32_t a_base, int kk) {
        uint32_t b_base = a_base + HALF_BYTES;
#pragma unroll
        for (int mt = 0; mt < 4; mt++) {
            uint32_t addr = a_base + ((wm * 64 + mt * 16 + lr) * KPADH + kk + lk) * 2;
            ldsm4(af[mt], addr);
        }
#pragma unroll
        for (int p = 0; p < 2; p++) {
            uint32_t r[4];
            uint32_t addr = b_base + ((wn * 32 + p * 16 + lr) * KPADH + kk + lk) * 2;
            ldsm4(r, addr);
            bf[2 * p][0] = r[0];     bf[2 * p][1] = r[2];
            bf[2 * p + 1][0] = r[1]; bf[2 * p + 1][1] = r[3];
        }
    };
    auto mma_all = [&](uint32_t af[4][4], uint32_t bf[4][2]) {
#pragma unroll
        for (int mt = 0; mt < 4; mt++)
#pragma unroll
            for (int nt = 0; nt < 4; nt++)
                mma16816(c[mt][nt], af[mt], bf[nt]);
    };

#pragma unroll
    for (int s = 0; s < STG - 1; s++) {
        load_stage(s, s);
        CP_COMMIT();
    }

    uint32_t afA[4][4], bfA[4][2], afB[4][4], bfB[4][2];
    CP_WAIT(STG - 2);
    __syncthreads();
    ldsm_group(afA, bfA, smem_u, 0);

    int buf = 0;
    for (int t = 0; t < KT2; t++) {
        uint32_t base = smem_u + buf * STAGE_BYTES;
        int nbuf = (buf + 1 == STG) ? 0 : buf + 1;

        ldsm_group(afB, bfB, base, 16);
        mma_all(afA, bfA);

        if (t + 1 < KT2) CP_WAIT(1);
        mma_all(afB, bfB);

        __syncthreads();
        if (t + 1 < KT2)
            ldsm_group(afA, bfA, smem_u + nbuf * STAGE_BYTES, 0);
        if (t + STG - 1 < KT2) {
            int lb = buf + (STG - 1);
            if (lb >= STG) lb -= STG;
            load_stage(t + STG - 1, lb);
        }
        CP_COMMIT();
        buf = nbuf;
    }

    // ---------------- epilogue ----------------
    if (EPI == 2 && bn == 8) {
#pragma unroll
        for (int mt = 0; mt < 4; mt++) {
            int r0 = bm * 128 + wm * 64 + mt * 16 + gid;
            int b0 = r0 >> 12, n0 = r0 & (N_ - 1);
            int r1 = r0 + 8;
            int b1v = r1 >> 12, n1 = r1 & (N_ - 1);
#pragma unroll
            for (int nt = 0; nt < 4; nt++) {
                int col = wn * 32 + nt * 8 + tig * 2;
                if (col < 48) {
#pragma unroll
                    for (int q = 0; q < 2; q++) {
                        int cl = col + q;
                        int which = cl >> 4, h = cl & 15;
                        float p1a = (which == 0) ? g_p1[h * N_ + n0] : 0.f;
                        float p1b = (which == 0) ? g_p1[h * N_ + n1] : 0.f;
                        proj_store(c[mt][nt][q] + p1a, which, h, b0, n0);
                        proj_store(c[mt][nt][2 + q] + p1b, which, h, b1v, n1);
                    }
                }
            }
        }
        return;
    }

#pragma unroll
    for (int mt = 0; mt < 4; mt++) {
        int r0 = bm * 128 + wm * 64 + mt * 16 + gid;
#pragma unroll
        for (int nt = 0; nt < 4; nt++) {
            int col = bn * 128 + wn * 32 + nt * 8 + tig * 2;
            if (EPI == 1) {
                *(float2*)((float*)Cv + (size_t)r0 * 1024 + col) =
                    make_float2(c[mt][nt][0], c[mt][nt][1]);
                *(float2*)((float*)Cv + (size_t)(r0 + 8) * 1024 + col) =
                    make_float2(c[mt][nt][2], c[mt][nt][3]);
            } else {
                *(__half2*)((__half*)Cv + (size_t)r0 * 1024 + col) =
                    __floats2half2_rn(c[mt][nt][0], c[mt][nt][1]);
                *(__half2*)((__half*)Cv + (size_t)(r0 + 8) * 1024 + col) =
                    __floats2half2_rn(c[mt][nt][2], c[mt][nt][3]);
            }
        }
    }
}

// ---------------------------------------------------------------------------
// Fused scan, occupancy-split: grid = 64 bh x 4 a-slices = 256 blocks.
// ---------------------------------------------------------------------------
#define SCH 64                 // chunks per block
#define SCLEN (N_ / SCH)       // 64 n per chunk
#define ALANES 16              // a-lanes per block (A_/4)

__global__ __launch_bounds__(1024) void scan_fused() {
    __shared__ float s_cv[SCH][ALANES];
    __shared__ float s_c[SCH];

    int bh = blockIdx.x >> 2;
    int abase = (blockIdx.x & 3) * ALANES;
    int b = bh >> 4, h = bh & 15;
    int g = threadIdx.x >> 4;
    int a = abase + (threadIdx.x & 15);
    int n0 = g * SCLEN;

    const float* cr = g_cross + bh * N_;
    const float* dg = g_diag + bh * N_;
    const float* ex = g_extra + bh * N_;
    const float* pe = g_p2e + h * N_;

    float sc = 0.f, scv = 0.f;
#pragma unroll 8
    for (int i = 0; i < SCLEN; i++) {
        int n = n0 + i;
        float cn = cr[n];
        float v = __half2float(g_valh[((size_t)(b * N_ + n) * H_ + h) * A_ + a]);
        sc += cn;
        scv = fmaf(cn, v, scv);
    }
    s_cv[g][threadIdx.x & 15] = scv;
    if ((threadIdx.x & 15) == 0) s_c[g] = sc;
    __syncthreads();

    float run_cv = 0.f, run_c = 0.f;
#pragma unroll
    for (int j = 0; j < SCH; j++) {
        if (j < g) {
            run_cv += s_cv[j][threadIdx.x & 15];
            run_c += s_c[j];
        }
    }

#pragma unroll 8
    for (int i = 0; i < SCLEN; i++) {
        int n = n0 + i;
        float cn = cr[n];
        float dn = dg[n];
        float peE = pe[n] * ex[n];
        size_t vidx = ((size_t)(b * N_ + n) * H_ + h) * A_ + a;
        float v = __half2float(g_valh[vidx]);
        run_cv = fmaf(cn, v, run_cv);
        run_c += cn;
        float num = fmaf(run_cv, peE, v * dn);
        float den = fmaf(run_c, peE, dn);
        g_outh[vidx] = __float2half_rn(num / den);
    }
}

// ---------------------------------------------------------------------------
// Launcher
// ---------------------------------------------------------------------------
extern "C" void kernel_launch(void* const* d_in, const int* in_sizes, int n_in,
                              void* d_out, int out_size) {
    const float* x  = (const float*)d_in[0];
    const float* k1 = (const float*)d_in[1];
    const float* k2 = (const float*)d_in[2];
    const float* k3 = (const float*)d_in[3];
    const float* a1 = (const float*)d_in[4];
    const float* a2 = (const float*)d_in[5];
    const float* b1 = (const float*)d_in[6];
    const float* b2 = (const float*)d_in[7];
    const float* cc = (const float*)d_in[8];
    const float* vw = (const float*)d_in[9];
    const float* ow = (const float*)d_in[10];
    float* out = (float*)d_out;

    void *p_wve, *p_woh, *p_valh, *p_outh, *p_xh;
    cudaGetSymbolAddress(&p_wve, g_wv_e);
    cudaGetSymbolAddress(&p_woh, g_wo_h);
    cudaGetSymbolAddress(&p_valh, g_valh);
    cudaGetSymbolAddress(&p_outh, g_outh);
    cudaGetSymbolAddress(&p_xh, g_xh);

    cudaFuncSetAttribute(gemm_f16<2>, cudaFuncAttributeMaxDynamicSharedMemorySize, GSMEM);
    cudaFuncSetAttribute(gemm_f16<1>, cudaFuncAttributeMaxDynamicSharedMemorySize, GSMEM);

    prologue<<<PB_POS, 256>>>(x, vw, ow, k1, k2, k3, a1, a2, b1, b2, cc);

    // GEMM1 (fused proj): values cols 0..1023 -> g_valh; tile bn==8 -> exp scatter
    gemm_f16<2><<<dim3(9, 128), 256, GSMEM>>>((const __half*)p_xh,
                                              (const __half*)p_wve, p_valh);

    scan_fused<<<B_ * H_ * 4, 1024>>>();

    // result = outh @ Wo^T -> d_out (f32)
    gemm_f16<1><<<dim3(8, 128), 256, GSMEM>>>((const __half*)p_outh,
                                              (const __half*)p_woh, out);
}

// round 14
// speedup vs baseline: 1.0677x; 1.0677x over previous
#include <cuda_runtime.h>
#include <cuda_fp16.h>
#include <math.h>
#include <stdint.h>

// Problem shapes (fixed)
#define B_ 4
#define N_ 4096
#define W_ 1024
#define H_ 16
#define A_ 64
#define HA_ 1024           // H_*A_
#define M_ 16384           // B_*N_
#define NB1 1152           // GEMM1 extended N (1024 values + 48 proj + 80 pad)

// ---------------------------------------------------------------------------
// Scratch (no allocations allowed -> __device__ globals)
// ---------------------------------------------------------------------------
__device__ __half g_valh[M_ * HA_];         // 32 MB (GEMM1 out, fp16)
__device__ __half g_outh[M_ * HA_];         // 32 MB (GEMM2 in, fp16)
__device__ __half g_xh[M_ * W_];            // fp16 x, 32 MB
__device__ __half g_wv_e[NB1 * W_];         // extended GEMM1 B: 2.25 MB
__device__ __half g_wo_h[W_ * HA_];         // 2 MB
__device__ float g_cross[B_ * H_ * N_];
__device__ float g_diag [B_ * H_ * N_];
__device__ float g_extra[B_ * H_ * N_];
__device__ float g_p1 [H_ * N_];
__device__ float g_p2e[H_ * N_];

__device__ __forceinline__ uint32_t s2u(const void* p) {
    uint32_t r;
    asm("{ .reg .u64 t; cvta.to.shared.u64 t, %1; cvt.u32.u64 %0, t; }" : "=r"(r) : "l"(p));
    return r;
}
__device__ __forceinline__ void cp16(uint32_t dst, const void* src) {
    asm volatile("cp.async.cg.shared.global [%0], [%1], 16;" :: "r"(dst), "l"(src));
}
#define CP_COMMIT() asm volatile("cp.async.commit_group;" ::: "memory")
#define CP_WAIT(n)  asm volatile("cp.async.wait_group %0;" :: "n"(n) : "memory")

// ---------------------------------------------------------------------------
// Fused prologue: one launch, blockIdx-range dispatch, 256 threads/block.
// MUFU-heavy pos blocks FIRST so their latency tail overlaps the
// bandwidth-bound bulk.
//   [0, 256)             pos_kernel
//   [256, 8448)          convert_x        (x -> g_xh, 8 elems/thread)
//   [8448, 9472)         transpose_wv     (1024 tiles of 32x32)
//   [9472, 9984)         fill_proj_rows
//   [9984, 12032)        transpose_wo
// ---------------------------------------------------------------------------
#define PB_POS  256
#define PB_CONV (PB_POS + 8192)
#define PB_WV   (PB_CONV + 1024)
#define PB_PROJ (PB_WV + 512)
#define PB_WO   (PB_PROJ + 2048)

__global__ __launch_bounds__(256) void prologue(const float* __restrict__ x,
                                                const float* __restrict__ vw,
                                                const float* __restrict__ ow,
                                                const float* __restrict__ k1,
                                                const float* __restrict__ k2,
                                                const float* __restrict__ k3,
                                                const float* __restrict__ a1,
                                                const float* __restrict__ a2,
                                                const float* __restrict__ b1,
                                                const float* __restrict__ b2,
                                                const float* __restrict__ cc) {
    int blk = blockIdx.x;
    if (blk < PB_POS) {
        // ---- pos_kernel ----
        int idx = blk * 256 + threadIdx.x;             // 0..65535
        int h = idx >> 12;
        int n = idx & (N_ - 1);
        float nv = (float)n * (1.0f / 4095.0f);
        float s1 = 0.f, s2 = 0.f;
#pragma unroll 8
        for (int p = 0; p < 64; p++) {
            float cp = cc[h * 64 + p];
            s1 += sinf(fmaf(a1[h * 64 + p], nv, b1[h * 64 + p])) * cp;
            s2 += sinf(fmaf(a2[h * 64 + p], nv, b2[h * 64 + p])) * cp;
        }
        g_p1[idx] = s1;
        s2 = fminf(fmaxf(s2, -20.f), 20.f);
        g_p2e[idx] = expf(s2);
    } else if (blk < PB_CONV) {
        // ---- convert_x ----
        size_t i = ((size_t)(blk - PB_POS) * 256 + threadIdx.x) * 8;
        float4 v1 = *(const float4*)(x + i);
        float4 v2 = *(const float4*)(x + i + 4);
        __half2 h0 = __floats2half2_rn(v1.x, v1.y);
        __half2 h1 = __floats2half2_rn(v1.z, v1.w);
        __half2 h2 = __floats2half2_rn(v2.x, v2.y);
        __half2 h3 = __floats2half2_rn(v2.z, v2.w);
        *(uint4*)(g_xh + i) = make_uint4(*(uint32_t*)&h0, *(uint32_t*)&h1,
                                         *(uint32_t*)&h2, *(uint32_t*)&h3);
    } else if (blk < PB_WV) {
        // ---- transpose_wv ----
        __shared__ float tile[32][33];
        int t = blk - PB_CONV;          // 0..1023
        int h = t >> 6;
        int w0 = ((t >> 1) & 31) * 32;
        int a0 = (t & 1) * 32;
        int tx = threadIdx.x & 31;
        int ty = threadIdx.x >> 5;      // 0..7
#pragma unroll
        for (int i = 0; i < 4; i++) {
            int w = w0 + ty + i * 8;
            tile[ty + i * 8][tx] = vw[((h << 10) + w) * 64 + a0 + tx];
        }
        __syncthreads();
#pragma unroll
        for (int i = 0; i < 4; i++) {
            int a = a0 + ty + i * 8;
            g_wv_e[((h << 6) + a) * 1024 + w0 + tx] =
                __float2half_rn(tile[tx][ty + i * 8]);
        }
    } else if (blk < PB_PROJ) {
        // ---- fill_proj_rows ----
        int idx = (blk - PB_WV) * 256 + threadIdx.x;
        int j = idx >> 10;
        int w = idx & 1023;
        __half v = __float2half(0.f);
        if (j < 48) {
            const float* kk = (j < 16) ? k1 : ((j < 32) ? k2 : k3);
            v = __float2half_rn(kk[(j & 15) * W_ + w]);
        }
        g_wv_e[(size_t)(1024 + j) * 1024 + w] = v;
    } else {
        // ---- transpose_wo ----
        int i2 = ((blk - PB_PROJ) * 256 + threadIdx.x) * 2;
        int a = i2 & 63;
        int hq = (i2 >> 6) & 15;
        int w = i2 >> 10;
        float2 v = *(const float2*)(ow + (size_t)(((hq << 10) + w) << 6) + a);
        *(__half2*)(g_wo_h + i2) = __floats2half2_rn(v.x, v.y);
    }
}

// ---------------------------------------------------------------------------
// fp16 mma.m16n8k16 GEMM, cp.async 5-stage pipeline, prefetch after sync.
//      EPI: 1 = float C, 2 = half C + fused proj tile at bn==8
// ---------------------------------------------------------------------------
#define BK 32
#define KPADH 40
#define KT2 (1024 / BK)
#define STG 5
#define HALF_BYTES (128 * KPADH * 2)
#define STAGE_BYTES (2 * HALF_BYTES)
#define GSMEM (STG * STAGE_BYTES)      // 102400 B

__device__ __forceinline__ void mma16816(float* c, const uint32_t* a, const uint32_t* b) {
    asm volatile(
        "mma.sync.aligned.m16n8k16.row.col.f32.f16.f16.f32 "
        "{%0,%1,%2,%3}, {%4,%5,%6,%7}, {%8,%9}, {%0,%1,%2,%3};"
        : "+f"(c[0]), "+f"(c[1]), "+f"(c[2]), "+f"(c[3])
        : "r"(a[0]), "r"(a[1]), "r"(a[2]), "r"(a[3]), "r"(b[0]), "r"(b[1]));
}
__device__ __forceinline__ void ldsm4(uint32_t* r, uint32_t addr) {
    asm volatile("ldmatrix.sync.aligned.m8n8.x4.shared.b16 {%0,%1,%2,%3}, [%4];"
                 : "=r"(r[0]), "=r"(r[1]), "=r"(r[2]), "=r"(r[3]) : "r"(addr));
}

__device__ __forceinline__ void proj_store(float s, int which, int h, int b, int n) {
    s = fminf(fmaxf(s, -20.f), 20.f);
    s = expf(s);
    int off = (b * H_ + h) * N_ + n;
    if (which == 0)      g_cross[off] = s;
    else if (which == 1) g_diag[off]  = s;
    else                 g_extra[off] = s;
}

template <int EPI>
__global__ __launch_bounds__(256, 2) void gemm_f16(const __half* __restrict__ A,
                                                   const __half* __restrict__ Bt,
                                                   void* __restrict__ Cv) {
    extern __shared__ __align__(16) char smem[];
    uint32_t smem_u = s2u(smem);

    int tid = threadIdx.x;
    int lane = tid & 31, wid = tid >> 5;
    int wm = wid >> 2;
    int wn = wid & 3;
    int gid = lane >> 2;
    int tig = lane & 3;
    int lr = lane & 15;
    int lk = (lane >> 4) << 3;

    int bn = blockIdx.x, bm = blockIdx.y;
    const __half* Ag = A + (size_t)(bm * 128) * 1024;
    const __half* Bg = Bt + (size_t)(bn * 128) * 1024;

    int c0row = tid >> 2;
    int c0k = (tid & 3) * 8;

    float c[4][4][4];
#pragma unroll
    for (int i = 0; i < 4; i++)
#pragma unroll
        for (int j = 0; j < 4; j++)
#pragma unroll
            for (int q = 0; q < 4; q++) c[i][j][q] = 0.f;

    auto load_stage = [&](int t, int s) {
        int k0 = t * BK;
        uint32_t base = smem_u + s * STAGE_BYTES;
#pragma unroll
        for (int i = 0; i < 2; i++) {
            int row = c0row + i * 64;
            uint32_t off = (uint32_t)(row * (KPADH * 2) + c0k * 2);
            cp16(base + off, Ag + (size_t)row * 1024 + k0 + c0k);
            cp16(base + HALF_BYTES + off, Bg + (size_t)row * 1024 + k0 + c0k);
        }
    };
    auto ldsm_group = [&](uint32_t af[4][4], uint32_t bf[4][2],
                          uint32_t a_base, int kk) {
        uint32_t b_base = a_base + HALF_BYTES;
#pragma unroll
        for (int mt = 0; mt < 4; mt++) {
            uint32_t addr = a_base + ((wm * 64 + mt * 16 + lr) * KPADH + kk + lk) * 2;
            ldsm4(af[mt], addr);
        }
#pragma unroll
        for (int p = 0; p < 2; p++) {
            uint32_t r[4];
            uint32_t addr = b_base + ((wn * 32 + p * 16 + lr) * KPADH + kk + lk) * 2;
            ldsm4(r, addr);
            bf[2 * p][0] = r[0];     bf[2 * p][1] = r[2];
            bf[2 * p + 1][0] = r[1]; bf[2 * p + 1][1] = r[3];
        }
    };
    auto mma_all = [&](uint32_t af[4][4], uint32_t bf[4][2]) {
#pragma unroll
        for (int mt = 0; mt < 4; mt++)
#pragma unroll
            for (int nt = 0; nt < 4; nt++)
                mma16816(c[mt][nt], af[mt], bf[nt]);
    };

#pragma unroll
    for (int s = 0; s < STG - 1; s++) {
        load_stage(s, s);
        CP_COMMIT();
    }

    uint32_t afA[4][4], bfA[4][2], afB[4][4], bfB[4][2];
    CP_WAIT(STG - 2);          // stage 0 retired (own)
    __syncthreads();           // stage 0 visible to all threads
    ldsm_group(afA, bfA, smem_u, 0);

    int buf = 0;
    for (int t = 0; t < KT2; t++) {
        uint32_t base = smem_u + buf * STAGE_BYTES;
        int nbuf = (buf + 1 == STG) ? 0 : buf + 1;

        ldsm_group(afB, bfB, base, 16);   // g1 of current tile
        mma_all(afA, bfA);                // g0 MMAs overlap g1 ldsm latency

        if (t + 1 < KT2) CP_WAIT(STG - 3);  // stage t+1 retired (own)
        mma_all(afB, bfB);                  // g1 MMAs

        __syncthreads();                  // stage t+1 visible to all threads
        if (t + 1 < KT2)
            ldsm_group(afA, bfA, smem_u + nbuf * STAGE_BYTES, 0);  // prefetch g0
        if (t + STG - 1 < KT2) {
            int lb = buf + (STG - 1);
            if (lb >= STG) lb -= STG;
            load_stage(t + STG - 1, lb);
        }
        CP_COMMIT();
        buf = nbuf;
    }

    // ---------------- epilogue ----------------
    if (EPI == 2 && bn == 8) {
#pragma unroll
        for (int mt = 0; mt < 4; mt++) {
            int r0 = bm * 128 + wm * 64 + mt * 16 + gid;
            int b0 = r0 >> 12, n0 = r0 & (N_ - 1);
            int r1 = r0 + 8;
            int b1v = r1 >> 12, n1 = r1 & (N_ - 1);
#pragma unroll
            for (int nt = 0; nt < 4; nt++) {
                int col = wn * 32 + nt * 8 + tig * 2;
                if (col < 48) {
#pragma unroll
                    for (int q = 0; q < 2; q++) {
                        int cl = col + q;
                        int which = cl >> 4, h = cl & 15;
                        float p1a = (which == 0) ? g_p1[h * N_ + n0] : 0.f;
                        float p1b = (which == 0) ? g_p1[h * N_ + n1] : 0.f;
                        proj_store(c[mt][nt][q] + p1a, which, h, b0, n0);
                        proj_store(c[mt][nt][2 + q] + p1b, which, h, b1v, n1);
                    }
                }
            }
        }
        return;
    }

#pragma unroll
    for (int mt = 0; mt < 4; mt++) {
        int r0 = bm * 128 + wm * 64 + mt * 16 + gid;
#pragma unroll
        for (int nt = 0; nt < 4; nt++) {
            int col = bn * 128 + wn * 32 + nt * 8 + tig * 2;
            if (EPI == 1) {
                *(float2*)((float*)Cv + (size_t)r0 * 1024 + col) =
                    make_float2(c[mt][nt][0], c[mt][nt][1]);
                *(float2*)((float*)Cv + (size_t)(r0 + 8) * 1024 + col) =
                    make_float2(c[mt][nt][2], c[mt][nt][3]);
            } else {
                *(__half2*)((__half*)Cv + (size_t)r0 * 1024 + col) =
                    __floats2half2_rn(c[mt][nt][0], c[mt][nt][1]);
                *(__half2*)((__half*)Cv + (size_t)(r0 + 8) * 1024 + col) =
                    __floats2half2_rn(c[mt][nt][2], c[mt][nt][3]);
            }
        }
    }
}

// ---------------------------------------------------------------------------
// Fused scan, occupancy-split: grid = 64 bh x 4 a-slices = 256 blocks.
// ---------------------------------------------------------------------------
#define SCH 64                 // chunks per block
#define SCLEN (N_ / SCH)       // 64 n per chunk
#define ALANES 16              // a-lanes per block (A_/4)

__global__ __launch_bounds__(1024) void scan_fused() {
    __shared__ float s_cv[SCH][ALANES];
    __shared__ float s_c[SCH];

    int bh = blockIdx.x >> 2;
    int abase = (blockIdx.x & 3) * ALANES;
    int b = bh >> 4, h = bh & 15;
    int g = threadIdx.x >> 4;
    int a = abase + (threadIdx.x & 15);
    int n0 = g * SCLEN;

    const float* cr = g_cross + bh * N_;
    const float* dg = g_diag + bh * N_;
    const float* ex = g_extra + bh * N_;
    const float* pe = g_p2e + h * N_;

    float sc = 0.f, scv = 0.f;
#pragma unroll 8
    for (int i = 0; i < SCLEN; i++) {
        int n = n0 + i;
        float cn = cr[n];
        float v = __half2float(g_valh[((size_t)(b * N_ + n) * H_ + h) * A_ + a]);
        sc += cn;
        scv = fmaf(cn, v, scv);
    }
    s_cv[g][threadIdx.x & 15] = scv;
    if ((threadIdx.x & 15) == 0) s_c[g] = sc;
    __syncthreads();

    float run_cv = 0.f, run_c = 0.f;
#pragma unroll
    for (int j = 0; j < SCH; j++) {
        if (j < g) {
            run_cv += s_cv[j][threadIdx.x & 15];
            run_c += s_c[j];
        }
    }

#pragma unroll 8
    for (int i = 0; i < SCLEN; i++) {
        int n = n0 + i;
        float cn = cr[n];
        float dn = dg[n];
        float peE = pe[n] * ex[n];
        size_t vidx = ((size_t)(b * N_ + n) * H_ + h) * A_ + a;
        float v = __half2float(g_valh[vidx]);
        run_cv = fmaf(cn, v, run_cv);
        run_c += cn;
        float num = fmaf(run_cv, peE, v * dn);
        float den = fmaf(run_c, peE, dn);
        g_outh[vidx] = __float2half_rn(num / den);
    }
}

// ---------------------------------------------------------------------------
// Launcher
// ---------------------------------------------------------------------------
extern "C" void kernel_launch(void* const* d_in, const int* in_sizes, int n_in,
                              void* d_out, int out_size) {
    const float* x  = (const float*)d_in[0];
    const float* k1 = (const float*)d_in[1];
    const float* k2 = (const float*)d_in[2];
    const float* k3 = (const float*)d_in[3];
    const float* a1 = (const float*)d_in[4];
    const float* a2 = (const float*)d_in[5];
    const float* b1 = (const float*)d_in[6];
    const float* b2 = (const float*)d_in[7];
    const float* cc = (const float*)d_in[8];
    const float* vw = (const float*)d_in[9];
    const float* ow = (const float*)d_in[10];
    float* out = (float*)d_out;

    void *p_wve, *p_woh, *p_valh, *p_outh, *p_xh;
    cudaGetSymbolAddress(&p_wve, g_wv_e);
    cudaGetSymbolAddress(&p_woh, g_wo_h);
    cudaGetSymbolAddress(&p_valh, g_valh);
    cudaGetSymbolAddress(&p_outh, g_outh);
    cudaGetSymbolAddress(&p_xh, g_xh);

    cudaFuncSetAttribute(gemm_f16<2>, cudaFuncAttributeMaxDynamicSharedMemorySize, GSMEM);
    cudaFuncSetAttribute(gemm_f16<1>, cudaFuncAttributeMaxDynamicSharedMemorySize, GSMEM);

    prologue<<<PB_WO, 256>>>(x, vw, ow, k1, k2, k3, a1, a2, b1, b2, cc);

    // GEMM1 (fused proj): values cols 0..1023 -> g_valh; tile bn==8 -> exp scatter
    gemm_f16<2><<<dim3(9, 128), 256, GSMEM>>>((const __half*)p_xh,
                                              (const __half*)p_wve, p_valh);

    scan_fused<<<B_ * H_ * 4, 1024>>>();

    // result = outh @ Wo^T -> d_out (f32)
    gemm_f16<1><<<dim3(8, 128), 256, GSMEM>>>((const __half*)p_outh,
                                              (const __half*)p_woh, out);
}